// round 14
// baseline (speedup 1.0000x reference)
#include <cuda_runtime.h>
#include <cuda_fp16.h>
#include <math.h>

typedef unsigned long long ull;

#define BB 512
#define NSV 128
#define NTRK 512
#define KK 8
#define HH 16
#define TPB 128

__device__ float g_partial[2 * BB];
__device__ int   g_count[BB];          // zero-init BSS; self-resetting each run

__device__ __forceinline__ ull pack2(float lo, float hi) {
    ull r; asm("mov.b64 %0, {%1, %2};" : "=l"(r) : "f"(lo), "f"(hi)); return r;
}
__device__ __forceinline__ void unpack2(ull v, float& lo, float& hi) {
    asm("mov.b64 {%0, %1}, %2;" : "=f"(lo), "=f"(hi) : "l"(v));
}
__device__ __forceinline__ ull fma2(ull a, ull b, ull c) {
    ull d; asm("fma.rn.f32x2 %0, %1, %2, %3;" : "=l"(d) : "l"(a), "l"(b), "l"(c)); return d;
}
__device__ __forceinline__ float elu_f(float x) { return x > 0.0f ? x : __expf(x) - 1.0f; }

#define CE(a, b) { float _lo = fminf(a, b); b = fmaxf(a, b); a = _lo; }

__device__ __forceinline__ void sort8(float c[8]) {
    CE(c[0], c[1]); CE(c[2], c[3]); CE(c[4], c[5]); CE(c[6], c[7]);
    CE(c[0], c[2]); CE(c[1], c[3]); CE(c[4], c[6]); CE(c[5], c[7]);
    CE(c[1], c[2]); CE(c[5], c[6]);
    CE(c[0], c[4]); CE(c[1], c[5]); CE(c[2], c[6]); CE(c[3], c[7]);
    CE(c[2], c[4]); CE(c[3], c[5]);
    CE(c[1], c[2]); CE(c[3], c[4]); CE(c[5], c[6]);
}

__device__ __forceinline__ void merge8(float A[8], const float c[8]) {
    #pragma unroll
    for (int i = 0; i < 8; ++i) A[i] = fminf(A[i], c[7 - i]);
    CE(A[0], A[4]); CE(A[1], A[5]); CE(A[2], A[6]); CE(A[3], A[7]);
    CE(A[0], A[2]); CE(A[1], A[3]); CE(A[4], A[6]); CE(A[5], A[7]);
    CE(A[0], A[1]); CE(A[2], A[3]); CE(A[4], A[5]); CE(A[6], A[7]);
}

// MLP + logit-scalar + fp16 (-2*tf) vectors for two tracks sharing weight-row loads
__device__ __forceinline__ void mlp_pair(
    const float* __restrict__ xt0, const float* __restrict__ xt1,
    const float (*W1t_)[HH], const float (*W2t_)[HH],
    const float* b1t_, const float* b2t_, const float* wv_, float cst,
    float& accA, float& accB, __half2 mhA[8], __half2 mhB[8])
{
    const float4* p0 = reinterpret_cast<const float4*>(xt0);
    const float4* p1 = reinterpret_cast<const float4*>(xt1);
    const float4 a0 = p0[0], a1 = p0[1], b0 = p1[0], b1 = p1[1];
    const float xv0[8] = {a0.x, a0.y, a0.z, a0.w, a1.x, a1.y, a1.z, a1.w};
    const float xv1[8] = {b0.x, b0.y, b0.z, b0.w, b1.x, b1.y, b1.z, b1.w};

    ull hA[8], hB[8];
    #pragma unroll
    for (int p = 0; p < 8; ++p) {
        ull bb = *reinterpret_cast<const ull*>(&b1t_[2 * p]);
        hA[p] = bb; hB[p] = bb;
    }
    #pragma unroll
    for (int j = 0; j < 8; ++j) {
        const ulonglong2* row = reinterpret_cast<const ulonglong2*>(W1t_[j]);
        ulonglong2 r0 = row[0], r1 = row[1], r2 = row[2], r3 = row[3];
        ull xj0 = pack2(xv0[j], xv0[j]);
        ull xj1 = pack2(xv1[j], xv1[j]);
        hA[0] = fma2(xj0, r0.x, hA[0]); hA[1] = fma2(xj0, r0.y, hA[1]);
        hA[2] = fma2(xj0, r1.x, hA[2]); hA[3] = fma2(xj0, r1.y, hA[3]);
        hA[4] = fma2(xj0, r2.x, hA[4]); hA[5] = fma2(xj0, r2.y, hA[5]);
        hA[6] = fma2(xj0, r3.x, hA[6]); hA[7] = fma2(xj0, r3.y, hA[7]);
        hB[0] = fma2(xj1, r0.x, hB[0]); hB[1] = fma2(xj1, r0.y, hB[1]);
        hB[2] = fma2(xj1, r1.x, hB[2]); hB[3] = fma2(xj1, r1.y, hB[3]);
        hB[4] = fma2(xj1, r2.x, hB[4]); hB[5] = fma2(xj1, r2.y, hB[5]);
        hB[6] = fma2(xj1, r3.x, hB[6]); hB[7] = fma2(xj1, r3.y, hB[7]);
    }
    float ea[HH], eb[HH];
    #pragma unroll
    for (int p = 0; p < 8; ++p) {
        unpack2(hA[p], ea[2 * p], ea[2 * p + 1]);
        unpack2(hB[p], eb[2 * p], eb[2 * p + 1]);
    }
    #pragma unroll
    for (int h = 0; h < HH; ++h) { ea[h] = elu_f(ea[h]); eb[h] = elu_f(eb[h]); }

    ull tA[8], tB[8];
    #pragma unroll
    for (int p = 0; p < 8; ++p) {
        ull bb = *reinterpret_cast<const ull*>(&b2t_[2 * p]);
        tA[p] = bb; tB[p] = bb;
    }
    #pragma unroll
    for (int j = 0; j < HH; ++j) {
        const ulonglong2* row = reinterpret_cast<const ulonglong2*>(W2t_[j]);
        ulonglong2 r0 = row[0], r1 = row[1], r2 = row[2], r3 = row[3];
        ull hj0 = pack2(ea[j], ea[j]);
        ull hj1 = pack2(eb[j], eb[j]);
        tA[0] = fma2(hj0, r0.x, tA[0]); tA[1] = fma2(hj0, r0.y, tA[1]);
        tA[2] = fma2(hj0, r1.x, tA[2]); tA[3] = fma2(hj0, r1.y, tA[3]);
        tA[4] = fma2(hj0, r2.x, tA[4]); tA[5] = fma2(hj0, r2.y, tA[5]);
        tA[6] = fma2(hj0, r3.x, tA[6]); tA[7] = fma2(hj0, r3.y, tA[7]);
        tB[0] = fma2(hj1, r0.x, tB[0]); tB[1] = fma2(hj1, r0.y, tB[1]);
        tB[2] = fma2(hj1, r1.x, tB[2]); tB[3] = fma2(hj1, r1.y, tB[3]);
        tB[4] = fma2(hj1, r2.x, tB[4]); tB[5] = fma2(hj1, r2.y, tB[5]);
        tB[6] = fma2(hj1, r3.x, tB[6]); tB[7] = fma2(hj1, r3.y, tB[7]);
    }

    ull va = pack2(0.0f, 0.0f), vb = pack2(0.0f, 0.0f);
    #pragma unroll
    for (int p = 0; p < 8; ++p) {
        ull wp = *reinterpret_cast<const ull*>(&wv_[2 * p]);
        va = fma2(tA[p], wp, va);
        vb = fma2(tB[p], wp, vb);
    }
    float l, h;
    unpack2(va, l, h); accA = cst + l + h;
    unpack2(vb, l, h); accB = cst + l + h;

    // fp16 (-2*tf) pairs for the selection dot products
    #pragma unroll
    for (int p = 0; p < 8; ++p) {
        float lo, hi;
        unpack2(tA[p], lo, hi);
        mhA[p] = __floats2half2_rn(-2.0f * lo, -2.0f * hi);
        unpack2(tB[p], lo, hi);
        mhB[p] = __floats2half2_rn(-2.0f * lo, -2.0f * hi);
    }
}

// one CTA = one half-batch (256 tracks); last CTA of each pair combines
__global__ __launch_bounds__(TPB, 6)
void fused_gnn_kernel(
    const float* __restrict__ x_sv,   // (B*NSV, 2)
    const float* __restrict__ x_trk,  // (B*NTRK, 8)
    const float* __restrict__ W1s, const float* __restrict__ b1s,
    const float* __restrict__ W2s, const float* __restrict__ b2s,
    const float* __restrict__ W1t, const float* __restrict__ b1t,
    const float* __restrict__ W2t, const float* __restrict__ b2t,
    const float* __restrict__ We,  const float* __restrict__ be,
    const float* __restrict__ Wo,  const float* __restrict__ bo,
    float* __restrict__ out, int out_size)
{
    // fp16 SV rows for selection: 8 feature half2 pairs + (ssq,0) half2, stride 12 (48B, 16B-aligned)
    __shared__ __align__(16) __half2 s_svh[NSV][12];
    __shared__ __align__(16) float s_proj[NSV][20];   // fp32 output path
    __shared__ __align__(16) float s_W1t[8][HH];
    __shared__ __align__(16) float s_W2t[HH][HH];
    __shared__ __align__(16) float s_W2s[HH][HH];
    __shared__ __align__(16) float s_WeB[HH][HH];
    __shared__ __align__(16) float s_b1t[HH], s_b2t[HH], s_wv[HH], s_Wo[HH];
    __shared__ float s_const;
    __shared__ float s_warpsum[4];

    const int b    = blockIdx.x >> 1;
    const int half = blockIdx.x & 1;
    const int tid  = threadIdx.x;

    // ---- stage weights ----
    for (int i = tid; i < 8 * HH; i += TPB) s_W1t[i / HH][i % HH] = W1t[i];
    for (int i = tid; i < HH * HH; i += TPB) {
        int j = i / HH, h = i % HH;
        s_W2t[j][h] = W2t[i];
        s_W2s[j][h] = W2s[i];
        s_WeB[j][h] = We[(HH + j) * HH + h];
    }
    if (tid < HH) {
        s_b1t[tid] = b1t[tid];
        s_b2t[tid] = b2t[tid];
        s_Wo[tid]  = Wo[tid];
        float acc = 0.0f;
        #pragma unroll
        for (int h = 0; h < HH; ++h)
            acc += (We[tid * HH + h] - We[(HH + tid) * HH + h]) * Wo[h];
        s_wv[tid] = acc;
    }
    if (tid == 0) {
        float c = bo[0];
        #pragma unroll
        for (int h = 0; h < HH; ++h) c += be[h] * Wo[h];
        s_const = c;
    }
    __syncthreads();

    // ---- SV prep: one SV per thread, f32x2 matvecs ----
    {
        const int sp = tid;
        const float x0 = x_sv[(size_t)(b * NSV + sp) * 2 + 0];
        const float x1 = x_sv[(size_t)(b * NSV + sp) * 2 + 1];
        float h1[HH];
        #pragma unroll
        for (int h = 0; h < HH; ++h)
            h1[h] = elu_f(fmaf(x0, W1s[h], fmaf(x1, W1s[HH + h], b1s[h])));

        // f = h1 @ W2s + b2s  (packed)
        ull f2[8];
        #pragma unroll
        for (int p = 0; p < 8; ++p)
            f2[p] = *reinterpret_cast<const ull*>(&b2s[2 * p]);
        #pragma unroll
        for (int j = 0; j < HH; ++j) {
            const ulonglong2* row = reinterpret_cast<const ulonglong2*>(s_W2s[j]);
            ulonglong2 r0 = row[0], r1 = row[1], r2 = row[2], r3 = row[3];
            ull hb = pack2(h1[j], h1[j]);
            f2[0] = fma2(hb, r0.x, f2[0]); f2[1] = fma2(hb, r0.y, f2[1]);
            f2[2] = fma2(hb, r1.x, f2[2]); f2[3] = fma2(hb, r1.y, f2[3]);
            f2[4] = fma2(hb, r2.x, f2[4]); f2[5] = fma2(hb, r2.y, f2[5]);
            f2[6] = fma2(hb, r3.x, f2[6]); f2[7] = fma2(hb, r3.y, f2[7]);
        }
        float f[HH];
        #pragma unroll
        for (int p = 0; p < 8; ++p) unpack2(f2[p], f[2 * p], f[2 * p + 1]);

        // ssq = |f|^2  (packed self-dot)
        ull sq2p = pack2(0.0f, 0.0f);
        #pragma unroll
        for (int p = 0; p < 8; ++p) sq2p = fma2(f2[p], f2[p], sq2p);
        float sl, sh;
        unpack2(sq2p, sl, sh);
        const float sq = sl + sh;

        // proj = f @ WeB  (packed)
        ull pr2[8];
        #pragma unroll
        for (int p = 0; p < 8; ++p) pr2[p] = pack2(0.0f, 0.0f);
        #pragma unroll
        for (int j = 0; j < HH; ++j) {
            const ulonglong2* row = reinterpret_cast<const ulonglong2*>(s_WeB[j]);
            ulonglong2 r0 = row[0], r1 = row[1], r2 = row[2], r3 = row[3];
            ull fb = pack2(f[j], f[j]);
            pr2[0] = fma2(fb, r0.x, pr2[0]); pr2[1] = fma2(fb, r0.y, pr2[1]);
            pr2[2] = fma2(fb, r1.x, pr2[2]); pr2[3] = fma2(fb, r1.y, pr2[3]);
            pr2[4] = fma2(fb, r2.x, pr2[4]); pr2[5] = fma2(fb, r2.y, pr2[5]);
            pr2[6] = fma2(fb, r3.x, pr2[6]); pr2[7] = fma2(fb, r3.y, pr2[7]);
        }
        #pragma unroll
        for (int p = 0; p < 8; ++p)
            *reinterpret_cast<ull*>(&s_proj[sp][2 * p]) = pr2[p];

        #pragma unroll
        for (int j = 0; j < 8; ++j)
            s_svh[sp][j] = __floats2half2_rn(f[2 * j], f[2 * j + 1]);
        s_svh[sp][8] = __floats2half2_rn(sq, 0.0f);
    }

    // ---- 2 tracks per thread ----
    float acc0, acc1;
    __half2 m0h[8], m1h[8];
    {
        const float* base = x_trk + (size_t)(b * NTRK + half * 256) * 8;
        mlp_pair(base + (size_t)tid * 8, base + (size_t)(tid + TPB) * 8,
                 s_W1t, s_W2t, s_b1t, s_b2t, s_wv, s_const, acc0, acc1, m0h, m1h);
    }
    __syncthreads();

    // ---- kNN: batch-8 top-8, fp16 dot products, 2 tracks per SV row load ----
    float A0[KK], A1[KK];
    #pragma unroll
    for (int k = 0; k < KK; ++k) {
        const float inf = __int_as_float(0x7f800000);
        A0[k] = inf; A1[k] = inf;
    }

#define KEYCHAIN(MH, OUT) { \
        __half2 a0_ = __hfma2(MH[0], q[0], sq2); \
        __half2 a1_ = __hmul2(MH[1], q[1]); \
        a0_ = __hfma2(MH[2], q[2], a0_); a1_ = __hfma2(MH[3], q[3], a1_); \
        a0_ = __hfma2(MH[4], q[4], a0_); a1_ = __hfma2(MH[5], q[5], a1_); \
        a0_ = __hfma2(MH[6], q[6], a0_); a1_ = __hfma2(MH[7], q[7], a1_); \
        __half2 t_ = __hadd2(a0_, a1_); \
        __half  h_ = __hadd(__low2half(t_), __high2half(t_)); \
        float k_ = __half2float(h_); \
        OUT = __uint_as_float(__float_as_uint(k_) | (unsigned)s); }
        // low 12 f32-mantissa bits are 0 after f16->f32 cvt; OR embeds index directly

    #pragma unroll 2
    for (int g = 0; g < NSV; g += 8) {
        float c0[8], c1[8];
        #pragma unroll
        for (int i = 0; i < 8; ++i) {
            const int s = g + i;
            const uint4* rp = reinterpret_cast<const uint4*>(s_svh[s]);
            uint4 u0 = rp[0], u1 = rp[1];
            __half2 q[8];
            q[0] = *reinterpret_cast<const __half2*>(&u0.x);
            q[1] = *reinterpret_cast<const __half2*>(&u0.y);
            q[2] = *reinterpret_cast<const __half2*>(&u0.z);
            q[3] = *reinterpret_cast<const __half2*>(&u0.w);
            q[4] = *reinterpret_cast<const __half2*>(&u1.x);
            q[5] = *reinterpret_cast<const __half2*>(&u1.y);
            q[6] = *reinterpret_cast<const __half2*>(&u1.z);
            q[7] = *reinterpret_cast<const __half2*>(&u1.w);
            const __half2 sq2 = s_svh[s][8];
            KEYCHAIN(m0h, c0[i]);
            KEYCHAIN(m1h, c1[i]);
        }
        sort8(c0); merge8(A0, c0);
        sort8(c1); merge8(A1, c1);
    }
#undef KEYCHAIN

    // ---- max-pool over neighbor projections + sigmoid ----
    float osum = 0.0f;
#define POOL(Aarr, accv) { \
        float pm[HH]; \
        _Pragma("unroll") \
        for (int h = 0; h < HH; ++h) pm[h] = __int_as_float(0xff800000); \
        _Pragma("unroll") \
        for (int k = 0; k < KK; ++k) { \
            int idx = (int)(__float_as_uint(Aarr[k]) & 0x7Fu); \
            const float4* pr_ = reinterpret_cast<const float4*>(s_proj[idx]); \
            const float4 p0 = pr_[0], p1 = pr_[1], p2 = pr_[2], p3 = pr_[3]; \
            pm[0]  = fmaxf(pm[0],  p0.x); pm[1]  = fmaxf(pm[1],  p0.y); \
            pm[2]  = fmaxf(pm[2],  p0.z); pm[3]  = fmaxf(pm[3],  p0.w); \
            pm[4]  = fmaxf(pm[4],  p1.x); pm[5]  = fmaxf(pm[5],  p1.y); \
            pm[6]  = fmaxf(pm[6],  p1.z); pm[7]  = fmaxf(pm[7],  p1.w); \
            pm[8]  = fmaxf(pm[8],  p2.x); pm[9]  = fmaxf(pm[9],  p2.y); \
            pm[10] = fmaxf(pm[10], p2.z); pm[11] = fmaxf(pm[11], p2.w); \
            pm[12] = fmaxf(pm[12], p3.x); pm[13] = fmaxf(pm[13], p3.y); \
            pm[14] = fmaxf(pm[14], p3.z); pm[15] = fmaxf(pm[15], p3.w); \
        } \
        float a_ = accv; \
        _Pragma("unroll") \
        for (int h = 0; h < HH; ++h) a_ = fmaf(pm[h], s_Wo[h], a_); \
        osum += 1.0f / (1.0f + __expf(-a_)); }

    POOL(A0, acc0);
    POOL(A1, acc1);
#undef POOL

    // ---- partial sum over this CTA's 256 tracks ----
    float v = osum;
    #pragma unroll
    for (int off = 16; off > 0; off >>= 1) v += __shfl_xor_sync(0xFFFFFFFFu, v, off);
    const int warp = tid >> 5;
    const int lane = tid & 31;
    if (lane == 0) s_warpsum[warp] = v;
    __syncthreads();

    // ---- last-CTA-done combine (deterministic: fixed-order read by one thread) ----
    if (tid == 0) {
        g_partial[blockIdx.x] = s_warpsum[0] + s_warpsum[1] + s_warpsum[2] + s_warpsum[3];
        __threadfence();
        int old = atomicAdd(&g_count[b], 1);
        if (old == 1) {
            __threadfence();
            volatile float* gp = g_partial;
            float p0 = gp[2 * b];
            float p1 = gp[2 * b + 1];
            out[b] = (p0 + p1) * (1.0f / (float)NTRK);
            if (BB + b < out_size) out[BB + b] = (float)b;
            g_count[b] = 0;   // reset for next graph replay
        }
    }
}

extern "C" void kernel_launch(void* const* d_in, const int* in_sizes, int n_in,
                              void* d_out, int out_size) {
    const float* x_sv = (const float*)d_in[0];
    const float* x_trk = (const float*)d_in[1];
    // d_in[2] = batch_sv, d_in[3] = batch_trk : deterministic repeats, unused
    const float* W1s = (const float*)d_in[4];
    const float* b1s = (const float*)d_in[5];
    const float* W2s = (const float*)d_in[6];
    const float* b2s = (const float*)d_in[7];
    const float* W1t = (const float*)d_in[8];
    const float* b1t = (const float*)d_in[9];
    const float* W2t = (const float*)d_in[10];
    const float* b2t = (const float*)d_in[11];
    const float* We  = (const float*)d_in[12];
    const float* be  = (const float*)d_in[13];
    const float* Wo  = (const float*)d_in[14];
    const float* bo  = (const float*)d_in[15];
    float* out = (float*)d_out;

    fused_gnn_kernel<<<2 * BB, TPB>>>(x_sv, x_trk,
                                      W1s, b1s, W2s, b2s,
                                      W1t, b1t, W2t, b2t,
                                      We, be, Wo, bo,
                                      out, out_size);
}

// round 16
// speedup vs baseline: 1.1005x; 1.1005x over previous
#include <cuda_runtime.h>
#include <cuda_fp16.h>
#include <math.h>

typedef unsigned long long ull;
typedef unsigned int u32;

#define BB 512
#define NSV 128
#define NTRK 512
#define KK 8
#define HH 16
#define TPB 128

#define KEYS_W 68                       // track-dim stride (floats), conflict-free STS
#define KEYS_PER_WARP (16 * KEYS_W)     // 1088 floats per warp
#define SVH_STRIDE 12                   // u32 per SV fp16 row (8 used, pad for banks)

__device__ float g_partial[2 * BB];
__device__ int   g_count[BB];           // zero-init BSS; self-resetting each run

__device__ __forceinline__ ull pack2(float lo, float hi) {
    ull r; asm("mov.b64 %0, {%1, %2};" : "=l"(r) : "f"(lo), "f"(hi)); return r;
}
__device__ __forceinline__ void unpack2(ull v, float& lo, float& hi) {
    asm("mov.b64 {%0, %1}, %2;" : "=f"(lo), "=f"(hi) : "l"(v));
}
__device__ __forceinline__ ull fma2(ull a, ull b, ull c) {
    ull d; asm("fma.rn.f32x2 %0, %1, %2, %3;" : "=l"(d) : "l"(a), "l"(b), "l"(c)); return d;
}
__device__ __forceinline__ float elu_f(float x) { return x > 0.0f ? x : __expf(x) - 1.0f; }

__device__ __forceinline__ void mma16816(
    float& c0, float& c1, float& c2, float& c3,
    u32 a0, u32 a1, u32 a2, u32 a3,
    u32 b0, u32 b1)
{
    asm volatile(
        "mma.sync.aligned.m16n8k16.row.col.f32.f16.f16.f32 "
        "{%0,%1,%2,%3}, {%4,%5,%6,%7}, {%8,%9}, {%0,%1,%2,%3};"
        : "+f"(c0), "+f"(c1), "+f"(c2), "+f"(c3)
        : "r"(a0), "r"(a1), "r"(a2), "r"(a3), "r"(b0), "r"(b1));
}

#define CE(a, b) { float _lo = fminf(a, b); b = fmaxf(a, b); a = _lo; }

__device__ __forceinline__ void sort8(float c[8]) {
    CE(c[0], c[1]); CE(c[2], c[3]); CE(c[4], c[5]); CE(c[6], c[7]);
    CE(c[0], c[2]); CE(c[1], c[3]); CE(c[4], c[6]); CE(c[5], c[7]);
    CE(c[1], c[2]); CE(c[5], c[6]);
    CE(c[0], c[4]); CE(c[1], c[5]); CE(c[2], c[6]); CE(c[3], c[7]);
    CE(c[2], c[4]); CE(c[3], c[5]);
    CE(c[1], c[2]); CE(c[3], c[4]); CE(c[5], c[6]);
}

__device__ __forceinline__ void merge8(float A[8], const float c[8]) {
    #pragma unroll
    for (int i = 0; i < 8; ++i) A[i] = fminf(A[i], c[7 - i]);
    CE(A[0], A[4]); CE(A[1], A[5]); CE(A[2], A[6]); CE(A[3], A[7]);
    CE(A[0], A[2]); CE(A[1], A[3]); CE(A[4], A[6]); CE(A[5], A[7]);
    CE(A[0], A[1]); CE(A[2], A[3]); CE(A[4], A[5]); CE(A[6], A[7]);
}

// MLP + logit-scalar + fp16 (-2*tf) vectors for two tracks sharing weight-row loads
__device__ __forceinline__ void mlp_pair(
    const float* __restrict__ xt0, const float* __restrict__ xt1,
    const float (*W1t_)[HH], const float (*W2t_)[HH],
    const float* b1t_, const float* b2t_, const float* wv_, float cst,
    float& accA, float& accB, __half2 mhA[8], __half2 mhB[8])
{
    const float4* p0 = reinterpret_cast<const float4*>(xt0);
    const float4* p1 = reinterpret_cast<const float4*>(xt1);
    const float4 a0 = p0[0], a1 = p0[1], b0 = p1[0], b1 = p1[1];
    const float xv0[8] = {a0.x, a0.y, a0.z, a0.w, a1.x, a1.y, a1.z, a1.w};
    const float xv1[8] = {b0.x, b0.y, b0.z, b0.w, b1.x, b1.y, b1.z, b1.w};

    ull hA[8], hB[8];
    #pragma unroll
    for (int p = 0; p < 8; ++p) {
        ull bb = *reinterpret_cast<const ull*>(&b1t_[2 * p]);
        hA[p] = bb; hB[p] = bb;
    }
    #pragma unroll
    for (int j = 0; j < 8; ++j) {
        const ulonglong2* row = reinterpret_cast<const ulonglong2*>(W1t_[j]);
        ulonglong2 r0 = row[0], r1 = row[1], r2 = row[2], r3 = row[3];
        ull xj0 = pack2(xv0[j], xv0[j]);
        ull xj1 = pack2(xv1[j], xv1[j]);
        hA[0] = fma2(xj0, r0.x, hA[0]); hA[1] = fma2(xj0, r0.y, hA[1]);
        hA[2] = fma2(xj0, r1.x, hA[2]); hA[3] = fma2(xj0, r1.y, hA[3]);
        hA[4] = fma2(xj0, r2.x, hA[4]); hA[5] = fma2(xj0, r2.y, hA[5]);
        hA[6] = fma2(xj0, r3.x, hA[6]); hA[7] = fma2(xj0, r3.y, hA[7]);
        hB[0] = fma2(xj1, r0.x, hB[0]); hB[1] = fma2(xj1, r0.y, hB[1]);
        hB[2] = fma2(xj1, r1.x, hB[2]); hB[3] = fma2(xj1, r1.y, hB[3]);
        hB[4] = fma2(xj1, r2.x, hB[4]); hB[5] = fma2(xj1, r2.y, hB[5]);
        hB[6] = fma2(xj1, r3.x, hB[6]); hB[7] = fma2(xj1, r3.y, hB[7]);
    }
    float ea[HH], eb[HH];
    #pragma unroll
    for (int p = 0; p < 8; ++p) {
        unpack2(hA[p], ea[2 * p], ea[2 * p + 1]);
        unpack2(hB[p], eb[2 * p], eb[2 * p + 1]);
    }
    #pragma unroll
    for (int h = 0; h < HH; ++h) { ea[h] = elu_f(ea[h]); eb[h] = elu_f(eb[h]); }

    ull tA[8], tB[8];
    #pragma unroll
    for (int p = 0; p < 8; ++p) {
        ull bb = *reinterpret_cast<const ull*>(&b2t_[2 * p]);
        tA[p] = bb; tB[p] = bb;
    }
    #pragma unroll
    for (int j = 0; j < HH; ++j) {
        const ulonglong2* row = reinterpret_cast<const ulonglong2*>(W2t_[j]);
        ulonglong2 r0 = row[0], r1 = row[1], r2 = row[2], r3 = row[3];
        ull hj0 = pack2(ea[j], ea[j]);
        ull hj1 = pack2(eb[j], eb[j]);
        tA[0] = fma2(hj0, r0.x, tA[0]); tA[1] = fma2(hj0, r0.y, tA[1]);
        tA[2] = fma2(hj0, r1.x, tA[2]); tA[3] = fma2(hj0, r1.y, tA[3]);
        tA[4] = fma2(hj0, r2.x, tA[4]); tA[5] = fma2(hj0, r2.y, tA[5]);
        tA[6] = fma2(hj0, r3.x, tA[6]); tA[7] = fma2(hj0, r3.y, tA[7]);
        tB[0] = fma2(hj1, r0.x, tB[0]); tB[1] = fma2(hj1, r0.y, tB[1]);
        tB[2] = fma2(hj1, r1.x, tB[2]); tB[3] = fma2(hj1, r1.y, tB[3]);
        tB[4] = fma2(hj1, r2.x, tB[4]); tB[5] = fma2(hj1, r2.y, tB[5]);
        tB[6] = fma2(hj1, r3.x, tB[6]); tB[7] = fma2(hj1, r3.y, tB[7]);
    }

    ull va = pack2(0.0f, 0.0f), vb = pack2(0.0f, 0.0f);
    #pragma unroll
    for (int p = 0; p < 8; ++p) {
        ull wp = *reinterpret_cast<const ull*>(&wv_[2 * p]);
        va = fma2(tA[p], wp, va);
        vb = fma2(tB[p], wp, vb);
    }
    float l, h;
    unpack2(va, l, h); accA = cst + l + h;
    unpack2(vb, l, h); accB = cst + l + h;

    #pragma unroll
    for (int p = 0; p < 8; ++p) {
        float lo, hi;
        unpack2(tA[p], lo, hi);
        mhA[p] = __floats2half2_rn(-2.0f * lo, -2.0f * hi);
        unpack2(tB[p], lo, hi);
        mhB[p] = __floats2half2_rn(-2.0f * lo, -2.0f * hi);
    }
}

// one CTA = one half-batch (256 tracks); keys via HMMA; last CTA of pair combines
__global__ __launch_bounds__(TPB, 6)
void fused_gnn_kernel(
    const float* __restrict__ x_sv,   // (B*NSV, 2)
    const float* __restrict__ x_trk,  // (B*NTRK, 8)
    const float* __restrict__ W1s, const float* __restrict__ b1s,
    const float* __restrict__ W2s, const float* __restrict__ b2s,
    const float* __restrict__ W1t, const float* __restrict__ b1t,
    const float* __restrict__ W2t, const float* __restrict__ b2t,
    const float* __restrict__ We,  const float* __restrict__ be,
    const float* __restrict__ Wo,  const float* __restrict__ bo,
    float* __restrict__ out, int out_size)
{
    __shared__ __align__(16) u32 s_svh[NSV * SVH_STRIDE];       // fp16 SV rows (B frags)
    __shared__ float s_ssqf[NSV];
    __shared__ __align__(16) float s_proj[NSV][20];             // fp32 output path
    __shared__ __align__(16) float s_keys[4 * KEYS_PER_WARP];   // per-warp key buffers
    __shared__ __align__(16) float s_b1t[HH], s_b2t[HH], s_wv[HH], s_Wo[HH];
    __shared__ float s_const;
    __shared__ float s_warpsum[4];

    // prologue-only weight matrices aliased into warp0's keys region (896 < 1088 floats)
    float (*s_W1t)[HH] = (float(*)[HH])(s_keys);
    float (*s_W2t)[HH] = (float(*)[HH])(s_keys + 128);
    float (*s_W2s)[HH] = (float(*)[HH])(s_keys + 384);
    float (*s_WeB)[HH] = (float(*)[HH])(s_keys + 640);

    const int b    = blockIdx.x >> 1;
    const int half = blockIdx.x & 1;
    const int tid  = threadIdx.x;
    const int warp = tid >> 5;
    const int lane = tid & 31;
    const int gr   = lane >> 2;   // groupID
    const int tg   = lane & 3;    // threadID_in_group

    // ---- stage weights ----
    for (int i = tid; i < 8 * HH; i += TPB) s_W1t[i / HH][i % HH] = W1t[i];
    for (int i = tid; i < HH * HH; i += TPB) {
        int j = i / HH, h = i % HH;
        s_W2t[j][h] = W2t[i];
        s_W2s[j][h] = W2s[i];
        s_WeB[j][h] = We[(HH + j) * HH + h];
    }
    if (tid < HH) {
        s_b1t[tid] = b1t[tid];
        s_b2t[tid] = b2t[tid];
        s_Wo[tid]  = Wo[tid];
        float acc = 0.0f;
        #pragma unroll
        for (int h = 0; h < HH; ++h)
            acc += (We[tid * HH + h] - We[(HH + tid) * HH + h]) * Wo[h];
        s_wv[tid] = acc;
    }
    if (tid == 0) {
        float c = bo[0];
        #pragma unroll
        for (int h = 0; h < HH; ++h) c += be[h] * Wo[h];
        s_const = c;
    }
    __syncthreads();

    // ---- SV prep: one SV per thread ----
    {
        const int sp = tid;
        const float x0 = x_sv[(size_t)(b * NSV + sp) * 2 + 0];
        const float x1 = x_sv[(size_t)(b * NSV + sp) * 2 + 1];
        float h1[HH];
        #pragma unroll
        for (int h = 0; h < HH; ++h)
            h1[h] = elu_f(fmaf(x0, W1s[h], fmaf(x1, W1s[HH + h], b1s[h])));

        ull f2[8];
        #pragma unroll
        for (int p = 0; p < 8; ++p)
            f2[p] = *reinterpret_cast<const ull*>(&b2s[2 * p]);
        #pragma unroll
        for (int j = 0; j < HH; ++j) {
            const ulonglong2* row = reinterpret_cast<const ulonglong2*>(s_W2s[j]);
            ulonglong2 r0 = row[0], r1 = row[1], r2 = row[2], r3 = row[3];
            ull hb = pack2(h1[j], h1[j]);
            f2[0] = fma2(hb, r0.x, f2[0]); f2[1] = fma2(hb, r0.y, f2[1]);
            f2[2] = fma2(hb, r1.x, f2[2]); f2[3] = fma2(hb, r1.y, f2[3]);
            f2[4] = fma2(hb, r2.x, f2[4]); f2[5] = fma2(hb, r2.y, f2[5]);
            f2[6] = fma2(hb, r3.x, f2[6]); f2[7] = fma2(hb, r3.y, f2[7]);
        }
        float f[HH];
        #pragma unroll
        for (int p = 0; p < 8; ++p) unpack2(f2[p], f[2 * p], f[2 * p + 1]);

        ull sq2p = pack2(0.0f, 0.0f);
        #pragma unroll
        for (int p = 0; p < 8; ++p) sq2p = fma2(f2[p], f2[p], sq2p);
        float sl, sh;
        unpack2(sq2p, sl, sh);
        s_ssqf[sp] = sl + sh;

        ull pr2[8];
        #pragma unroll
        for (int p = 0; p < 8; ++p) pr2[p] = pack2(0.0f, 0.0f);
        #pragma unroll
        for (int j = 0; j < HH; ++j) {
            const ulonglong2* row = reinterpret_cast<const ulonglong2*>(s_WeB[j]);
            ulonglong2 r0 = row[0], r1 = row[1], r2 = row[2], r3 = row[3];
            ull fb = pack2(f[j], f[j]);
            pr2[0] = fma2(fb, r0.x, pr2[0]); pr2[1] = fma2(fb, r0.y, pr2[1]);
            pr2[2] = fma2(fb, r1.x, pr2[2]); pr2[3] = fma2(fb, r1.y, pr2[3]);
            pr2[4] = fma2(fb, r2.x, pr2[4]); pr2[5] = fma2(fb, r2.y, pr2[5]);
            pr2[6] = fma2(fb, r3.x, pr2[6]); pr2[7] = fma2(fb, r3.y, pr2[7]);
        }
        #pragma unroll
        for (int p = 0; p < 8; ++p)
            *reinterpret_cast<ull*>(&s_proj[sp][2 * p]) = pr2[p];

        #pragma unroll
        for (int j = 0; j < 8; ++j) {
            __half2 v = __floats2half2_rn(f[2 * j], f[2 * j + 1]);
            s_svh[sp * SVH_STRIDE + j] = *reinterpret_cast<u32*>(&v);
        }
    }
    __syncthreads();

    // ---- 2 tracks per thread: MLPs ----
    float acc0, acc1;
    __half2 m0h[8], m1h[8];
    {
        const float* base = x_trk + (size_t)(b * NTRK + half * 256 + warp * 64) * 8;
        mlp_pair(base + (size_t)lane * 8, base + (size_t)(lane + 32) * 8,
                 s_W1t, s_W2t, s_b1t, s_b2t, s_wv, s_const, acc0, acc1, m0h, m1h);
    }
    // all warps must finish reading aliased weights before A-staging clobbers them
    __syncthreads();

    // ---- A staging + fragment loads (warp-local, reuses keys region) ----
    float* wkeys = s_keys + warp * KEYS_PER_WARP;
    u32 af[16];
    {
        u32* sAu = reinterpret_cast<u32*>(wkeys);
        #pragma unroll
        for (int p = 0; p < 8; ++p) {
            sAu[lane * 8 + p]        = *reinterpret_cast<u32*>(&m0h[p]);
            sAu[(lane + 32) * 8 + p] = *reinterpret_cast<u32*>(&m1h[p]);
        }
        __syncwarp();
        #pragma unroll
        for (int rb = 0; rb < 4; ++rb) {
            af[rb * 4 + 0] = sAu[(rb * 16 + gr) * 8 + tg];
            af[rb * 4 + 1] = sAu[(rb * 16 + gr + 8) * 8 + tg];
            af[rb * 4 + 2] = sAu[(rb * 16 + gr) * 8 + tg + 4];
            af[rb * 4 + 3] = sAu[(rb * 16 + gr + 8) * 8 + tg + 4];
        }
        __syncwarp();
    }

    // ---- kNN: 8 chunks of 16 SVs; HMMA keys -> smem -> scalar top-8 ----
    float A0[KK], A1[KK];
    #pragma unroll
    for (int k = 0; k < KK; ++k) {
        const float inf = __int_as_float(0x7f800000);
        A0[k] = inf; A1[k] = inf;
    }
    float* stb = wkeys + (tg * 2) * KEYS_W + gr;

    #pragma unroll 1
    for (int chunk = 0; chunk < 8; ++chunk) {
        const int svb = chunk * 16;
        // MMA phase: keys[sv][track] = -2 * (tf . sv)
        #pragma unroll
        for (int ct = 0; ct < 2; ++ct) {
            const int n = svb + ct * 8 + gr;
            u32 b0 = s_svh[n * SVH_STRIDE + tg];
            u32 b1 = s_svh[n * SVH_STRIDE + tg + 4];
            #pragma unroll
            for (int rb = 0; rb < 4; ++rb) {
                float c0 = 0.0f, c1 = 0.0f, c2 = 0.0f, c3 = 0.0f;
                mma16816(c0, c1, c2, c3,
                         af[rb * 4], af[rb * 4 + 1], af[rb * 4 + 2], af[rb * 4 + 3],
                         b0, b1);
                float* sp_ = stb + ct * (8 * KEYS_W) + rb * 16;
                sp_[0]          = c0;
                sp_[KEYS_W]     = c1;
                sp_[8]          = c2;
                sp_[KEYS_W + 8] = c3;
            }
        }
        __syncwarp();

        // sort phase
        float ssqv[16];
        #pragma unroll
        for (int j = 0; j < 16; ++j) ssqv[j] = s_ssqf[svb + j];
        #pragma unroll
        for (int t2 = 0; t2 < 2; ++t2) {
            const float* kp = wkeys + (lane + 32 * t2);
            float* A = t2 ? A1 : A0;
            float c[8];
            #pragma unroll
            for (int j = 0; j < 8; ++j) {
                float key = kp[j * KEYS_W] + ssqv[j];
                c[j] = __uint_as_float((__float_as_uint(key) & 0xFFFFFF80u) | (unsigned)(svb + j));
            }
            sort8(c); merge8(A, c);
            #pragma unroll
            for (int j = 0; j < 8; ++j) {
                float key = kp[(8 + j) * KEYS_W] + ssqv[8 + j];
                c[j] = __uint_as_float((__float_as_uint(key) & 0xFFFFFF80u) | (unsigned)(svb + 8 + j));
            }
            sort8(c); merge8(A, c);
        }
        __syncwarp();
    }

    // ---- max-pool over neighbor projections + sigmoid ----
    float osum = 0.0f;
#define POOL(Aarr, accv) { \
        float pm[HH]; \
        _Pragma("unroll") \
        for (int h = 0; h < HH; ++h) pm[h] = __int_as_float(0xff800000); \
        _Pragma("unroll") \
        for (int k = 0; k < KK; ++k) { \
            int idx = (int)(__float_as_uint(Aarr[k]) & 0x7Fu); \
            const float4* pr_ = reinterpret_cast<const float4*>(s_proj[idx]); \
            const float4 p0 = pr_[0], p1 = pr_[1], p2 = pr_[2], p3 = pr_[3]; \
            pm[0]  = fmaxf(pm[0],  p0.x); pm[1]  = fmaxf(pm[1],  p0.y); \
            pm[2]  = fmaxf(pm[2],  p0.z); pm[3]  = fmaxf(pm[3],  p0.w); \
            pm[4]  = fmaxf(pm[4],  p1.x); pm[5]  = fmaxf(pm[5],  p1.y); \
            pm[6]  = fmaxf(pm[6],  p1.z); pm[7]  = fmaxf(pm[7],  p1.w); \
            pm[8]  = fmaxf(pm[8],  p2.x); pm[9]  = fmaxf(pm[9],  p2.y); \
            pm[10] = fmaxf(pm[10], p2.z); pm[11] = fmaxf(pm[11], p2.w); \
            pm[12] = fmaxf(pm[12], p3.x); pm[13] = fmaxf(pm[13], p3.y); \
            pm[14] = fmaxf(pm[14], p3.z); pm[15] = fmaxf(pm[15], p3.w); \
        } \
        float a_ = accv; \
        _Pragma("unroll") \
        for (int h = 0; h < HH; ++h) a_ = fmaf(pm[h], s_Wo[h], a_); \
        osum += 1.0f / (1.0f + __expf(-a_)); }

    POOL(A0, acc0);
    POOL(A1, acc1);
#undef POOL

    // ---- partial sum over this CTA's 256 tracks ----
    float v = osum;
    #pragma unroll
    for (int off = 16; off > 0; off >>= 1) v += __shfl_xor_sync(0xFFFFFFFFu, v, off);
    if (lane == 0) s_warpsum[warp] = v;
    __syncthreads();

    // ---- last-CTA-done combine (deterministic fixed-order read) ----
    if (tid == 0) {
        g_partial[blockIdx.x] = s_warpsum[0] + s_warpsum[1] + s_warpsum[2] + s_warpsum[3];
        __threadfence();
        int old = atomicAdd(&g_count[b], 1);
        if (old == 1) {
            __threadfence();
            volatile float* gp = g_partial;
            float p0 = gp[2 * b];
            float p1 = gp[2 * b + 1];
            out[b] = (p0 + p1) * (1.0f / (float)NTRK);
            if (BB + b < out_size) out[BB + b] = (float)b;
            g_count[b] = 0;   // reset for next graph replay
        }
    }
}

extern "C" void kernel_launch(void* const* d_in, const int* in_sizes, int n_in,
                              void* d_out, int out_size) {
    const float* x_sv = (const float*)d_in[0];
    const float* x_trk = (const float*)d_in[1];
    // d_in[2] = batch_sv, d_in[3] = batch_trk : deterministic repeats, unused
    const float* W1s = (const float*)d_in[4];
    const float* b1s = (const float*)d_in[5];
    const float* W2s = (const float*)d_in[6];
    const float* b2s = (const float*)d_in[7];
    const float* W1t = (const float*)d_in[8];
    const float* b1t = (const float*)d_in[9];
    const float* W2t = (const float*)d_in[10];
    const float* b2t = (const float*)d_in[11];
    const float* We  = (const float*)d_in[12];
    const float* be  = (const float*)d_in[13];
    const float* Wo  = (const float*)d_in[14];
    const float* bo  = (const float*)d_in[15];
    float* out = (float*)d_out;

    fused_gnn_kernel<<<2 * BB, TPB>>>(x_sv, x_trk,
                                      W1s, b1s, W2s, b2s,
                                      W1t, b1t, W2t, b2t,
                                      We, be, Wo, bo,
                                      out, out_size);
}